// round 14
// baseline (speedup 1.0000x reference)
#include <cuda_runtime.h>
#include <cstdint>

#define B_  8
#define C_  21
#define D_  64
#define O_  128
#define HW_ 65536
#define N_TOT (B_ * HW_)

typedef unsigned long long ull;
typedef unsigned int uint;

#define FFMA2(acc, a, b) asm("fma.rn.f32x2 %0, %1, %2, %0;" : "+l"(acc) : "l"(a), "l"(b))
#define FADD2(acc, a)    asm("add.rn.f32x2 %0, %0, %1;"     : "+l"(acc) : "l"(a))

// ---------------- device scratch ---------------------------------------------
#define KS_CHUNKS 37                  // 37*8 = 296 blocks = exactly 2 waves
#define NVAL 252                      // 231 triangle + 21 sums
__device__ float g_Gp[KS_CHUNKS * B_ * NVAL];   // per-block stat partials
__device__ float g_W2T[B_ * C_ * O_];           // combined weights [b][c][o]
__device__ float g_partY[B_ * O_];
__device__ float g_partQ[B_ * O_];

// ---------------- helpers ------------------------------------------------------
__device__ __forceinline__ void cp16(void* dst, const void* src) {
    uint s = (uint)__cvta_generic_to_shared(dst);
    asm volatile("cp.async.cg.shared.global [%0], [%1], 16;" :: "r"(s), "l"(src));
}
#define CP_COMMIT() asm volatile("cp.async.commit_group;" ::: "memory")
#define CP_WAIT1()  asm volatile("cp.async.wait_group 1;" ::: "memory")
#define CP_WAIT0()  asm volatile("cp.async.wait_group 0;" ::: "memory")

__device__ __forceinline__ float pairsum(ull a) {
    return __uint_as_float((uint)(a & 0xffffffffu)) + __uint_as_float((uint)(a >> 32));
}
__device__ __forceinline__ ull lo64(float4 v) {
    return ((ull)__float_as_uint(v.y) << 32) | __float_as_uint(v.x);
}
__device__ __forceinline__ ull hi64(float4 v) {
    return ((ull)__float_as_uint(v.w) << 32) | __float_as_uint(v.z);
}
__device__ __forceinline__ ull dup2(float x) {
    ull r;
    asm("mov.b64 %0, {%1, %1};" : "=l"(r) : "f"(x));
    return r;
}
__device__ __forceinline__ float wredsum(float v) {
#pragma unroll
    for (int off = 16; off; off >>= 1) v += __shfl_xor_sync(0xffffffffu, v, off);
    return v;
}

// ---------------- kstats v9: G6 tasks reading smem-staged tiles ---------------
// grid (37, 8), 672 threads = 21 warps. Same task decomposition as R13 (G6,
// proven), but the mask tile (21 x 128 px) is staged ONCE via a 3-slot
// cp.async ring (kmain's proven sync pattern); warps read LDS instead of
// re-issuing 6x-redundant LDGs with 600-cycle latency.
template <int R0, int NR, int C0, int NC, bool DIAG>
__device__ __forceinline__ void gram_task(const float* __restrict__ mb,
                                          float (*sT)[C_][128],
                                          int u0, int u1, int tid,
                                          float* __restrict__ gp) {
    const int lane = tid & 31;

    ull acc[NR][NC];
    ull ss[NR];
#pragma unroll
    for (int i = 0; i < NR; i++) {
        ss[i] = 0ull;
#pragma unroll
        for (int j = 0; j < NC; j++) acc[i][j] = 0ull;
    }

    // each thread stages exactly one 16B unit per tile
    const int sc = tid >> 5;          // row 0..20
    const int sq = (tid & 31) * 4;    // float offset within 128-px row
    auto issue = [&](int u, int slot) {
        cp16(&sT[slot][sc][sq], mb + (size_t)sc * HW_ + u * 128 + sq);
        CP_COMMIT();
    };

    issue(u0, 0);
    if (u0 + 1 < u1) issue(u0 + 1, 1);

    int slot = 0;
#pragma unroll 1
    for (int u = u0; u < u1; u++) {
        if (u + 1 < u1) { CP_WAIT1(); } else { CP_WAIT0(); }
        __syncthreads();                       // slot(u) full; slot(u+2) free
        if (u + 2 < u1) {
            int ns = slot + 2; if (ns >= 3) ns -= 3;
            issue(u + 2, ns);                  // overlaps compute
        }

        ull ra[NR], rb[NR];
#pragma unroll
        for (int i = 0; i < NR; i++) {
            float4 v = reinterpret_cast<const float4*>(sT[slot][R0 + i])[lane];
            ra[i] = lo64(v); rb[i] = hi64(v);
            if (DIAG) { FADD2(ss[i], ra[i]); FADD2(ss[i], rb[i]); }
        }
        ull ca[NC], cb[NC];
#pragma unroll
        for (int j = 0; j < NC; j++) {
            if (DIAG) { ca[j] = ra[j]; cb[j] = rb[j]; }
            else {
                float4 v = reinterpret_cast<const float4*>(sT[slot][C0 + j])[lane];
                ca[j] = lo64(v); cb[j] = hi64(v);
            }
        }
#pragma unroll
        for (int i = 0; i < NR; i++)
#pragma unroll
            for (int j = 0; j < NC; j++) {
                if (DIAG && j > i) continue;   // lower triangle only
                FFMA2(acc[i][j], ra[i], ca[j]);
                FFMA2(acc[i][j], rb[i], cb[j]);
            }

        slot = (slot + 1 == 3) ? 0 : slot + 1;
    }

#pragma unroll
    for (int i = 0; i < NR; i++) {
#pragma unroll
        for (int j = 0; j < NC; j++) {
            if (DIAG && j > i) continue;
            float v = wredsum(pairsum(acc[i][j]));
            const int r = R0 + i, c = C0 + j;
            if (lane == 0) gp[r * (r + 1) / 2 + c] = v;
        }
        if (DIAG) {
            float v = wredsum(pairsum(ss[i]));
            if (lane == 0) gp[231 + R0 + i] = v;
        }
    }
}

__global__ __launch_bounds__(672) void kstats(const float* __restrict__ mask) {
    __shared__ __align__(16) float sT[3][C_][128];   // 32256 B

    const int b = blockIdx.y;
    const int bidx = blockIdx.x;
    const int tid = threadIdx.x;
    const int wid = tid >> 5;

    const int u0 = (bidx * 512) / KS_CHUNKS;
    const int u1 = ((bidx + 1) * 512) / KS_CHUNKS;

    const float* mb = mask + (size_t)b * C_ * HW_;
    float* gp = g_Gp + (bidx * B_ + b) * NVAL;

    switch (wid) {
        case 0:  gram_task< 0, 4,  0, 4, true >(mb, sT, u0, u1, tid, gp); break;
        case 1:  gram_task< 4, 4,  4, 4, true >(mb, sT, u0, u1, tid, gp); break;
        case 2:  gram_task< 8, 4,  8, 4, true >(mb, sT, u0, u1, tid, gp); break;
        case 3:  gram_task<12, 3, 12, 3, true >(mb, sT, u0, u1, tid, gp); break;
        case 4:  gram_task<15, 3, 15, 3, true >(mb, sT, u0, u1, tid, gp); break;
        case 5:  gram_task<18, 3, 18, 3, true >(mb, sT, u0, u1, tid, gp); break;
        case 6:  gram_task< 4, 4,  0, 4, false>(mb, sT, u0, u1, tid, gp); break;
        case 7:  gram_task< 8, 4,  0, 4, false>(mb, sT, u0, u1, tid, gp); break;
        case 8:  gram_task< 8, 4,  4, 4, false>(mb, sT, u0, u1, tid, gp); break;
        case 9:  gram_task<12, 3,  0, 4, false>(mb, sT, u0, u1, tid, gp); break;
        case 10: gram_task<12, 3,  4, 4, false>(mb, sT, u0, u1, tid, gp); break;
        case 11: gram_task<12, 3,  8, 4, false>(mb, sT, u0, u1, tid, gp); break;
        case 12: gram_task<15, 3,  0, 4, false>(mb, sT, u0, u1, tid, gp); break;
        case 13: gram_task<15, 3,  4, 4, false>(mb, sT, u0, u1, tid, gp); break;
        case 14: gram_task<15, 3,  8, 4, false>(mb, sT, u0, u1, tid, gp); break;
        case 15: gram_task<15, 3, 12, 3, false>(mb, sT, u0, u1, tid, gp); break;
        case 16: gram_task<18, 3,  0, 4, false>(mb, sT, u0, u1, tid, gp); break;
        case 17: gram_task<18, 3,  4, 4, false>(mb, sT, u0, u1, tid, gp); break;
        case 18: gram_task<18, 3,  8, 4, false>(mb, sT, u0, u1, tid, gp); break;
        case 19: gram_task<18, 3, 12, 3, false>(mb, sT, u0, u1, tid, gp); break;
        default: gram_task<18, 3, 15, 3, false>(mb, sT, u0, u1, tid, gp); break;
    }
}

// ---------------- kprep_a: W2T + partial reduce + quadratic forms -------------
__global__ __launch_bounds__(256) void kprep_a(const float* __restrict__ feat,
                                               const float* __restrict__ conv_w) {
    __shared__ float sWT[D_ * 129 + 32];
    __shared__ float sF[C_ * D_];
    __shared__ float sG[231];
    __shared__ float sS[C_];
    const int b = blockIdx.x;
    const int tid = threadIdx.x;

    for (int i = tid; i < O_ * D_; i += 256) {
        int o = i >> 6, d = i & 63;
        sWT[d * 129 + o] = conv_w[i];
    }
    for (int i = tid; i < C_ * D_; i += 256) sF[i] = feat[b * C_ * D_ + i];
    for (int v = tid; v < NVAL; v += 256) {
        float s = 0.f;
#pragma unroll
        for (int ch = 0; ch < KS_CHUNKS; ch++) s += g_Gp[(ch * B_ + b) * NVAL + v];
        if (v < 231) sG[v] = s;
        else         sS[v - 231] = s;
    }
    __syncthreads();

    for (int idx = tid; idx < C_ * O_; idx += 256) {
        int c = idx >> 7, o = idx & 127;
        float s = 0.f;
#pragma unroll
        for (int d = 0; d < D_; d++)
            s = fmaf(sWT[d * 129 + o], sF[c * D_ + d], s);
        g_W2T[b * C_ * O_ + idx] = s;
    }
    __syncthreads();

    if (tid < O_) {
        const int o = tid;
        float w[C_];
#pragma unroll
        for (int c = 0; c < C_; c++) w[c] = g_W2T[(b * C_ + c) * O_ + o];
        float sumY = 0.f;
#pragma unroll
        for (int c = 0; c < C_; c++) sumY = fmaf(w[c], sS[c], sumY);
        float sumQ = 0.f;
#pragma unroll
        for (int r = 0; r < C_; r++) {
            const int tr = r * (r + 1) / 2;
            float t = sG[tr + r] * w[r];
#pragma unroll
            for (int c = 0; c < r; c++) t = fmaf(2.f * sG[tr + c], w[c], t);
            sumQ = fmaf(w[r], t, sumQ);
        }
        g_partY[b * O_ + o] = sumY;
        g_partQ[b * O_ + o] = sumQ;
    }
}

// ---------------- kmain: R13 core + pre-duplicated coefficients ---------------
// 148 blocks x 512 threads. Subtile = 256 px x 128 ch; 3-slot cp.async ring,
// one barrier per subtile. Coefs now stored f32x2-DUPLICATED in smem (dup done
// once per batch in stage()) -> inner loop: 4 uniform LDS.128 per (warp,c),
// zero dup2 ALU.
#define KM_NBLK 148
#define KM_NT   2048
#define KM_PX   256

__global__ __launch_bounds__(512) void kmain(const float* __restrict__ mask,
                                             float* __restrict__ out,
                                             const float* __restrict__ conv_b,
                                             const float* __restrict__ gamma,
                                             const float* __restrict__ beta) {
    __shared__ __align__(16) float sM[3][C_][KM_PX];   // 64512 B
    __shared__ __align__(16) ull  sCF2[C_ * O_];       // 21504 B (dup'd coefs)
    __shared__ __align__(16) float salpha[O_];
    __shared__ ull sbias2[O_];

    const int tid = threadIdx.x;
    const int wid = tid >> 5;
    const int lane = tid & 31;
    const int o0 = wid * 8;

    const int bid = blockIdx.x;
    const int t0 = (bid * KM_NT) / KM_NBLK;
    const int t1 = ((bid + 1) * KM_NT) / KM_NBLK;

    auto issue = [&](int s, int slot) {
        const int b = s >> 8;
        const int px = (s & 255) * KM_PX;
        const float* mb = mask + (size_t)b * C_ * HW_ + px;
        for (int u = tid; u < C_ * (KM_PX / 4); u += 512) {
            int c = u >> 6, q = u & 63;
            cp16(&sM[slot][c][q * 4], mb + (size_t)c * HW_ + q * 4);
        }
        CP_COMMIT();
    };
    auto stage = [&](int b) {
        const float2* src = reinterpret_cast<const float2*>(g_W2T + (size_t)b * C_ * O_);
        ulonglong2* dst = reinterpret_cast<ulonglong2*>(sCF2);
        for (int i = tid; i < C_ * O_ / 2; i += 512) {        // 1344
            float2 w = src[i];
            const float2 a = *reinterpret_cast<const float2*>(&salpha[(i << 1) & 127]);
            ulonglong2 d;
            d.x = dup2(w.x * a.x);
            d.y = dup2(w.y * a.y);
            dst[i] = d;
        }
    };

    // prologue: start the cp.async pipeline, then compute alpha/bias
    issue(t0, 0);
    if (t0 + 1 < t1) issue(t0 + 1, 1);

    if (tid < O_) {
        const int o = tid;
        float sumY = 0.f, sumQ = 0.f;
#pragma unroll
        for (int bb = 0; bb < B_; bb++) {
            sumY += g_partY[bb * O_ + o];
            sumQ += g_partQ[bb * O_ + o];
        }
        const float invN = 1.f / (float)N_TOT;
        const float b0 = conv_b[o];
        const float es = sumY * invN;
        const float mean = b0 + es;
        const float ey2 = sumQ * invN + 2.f * b0 * es + b0 * b0;
        const float var = ey2 - mean * mean;
        const float alpha = gamma[o] * rsqrtf(var + 1e-5f);
        salpha[o] = alpha;
        sbias2[o] = dup2(beta[o] + alpha * (b0 - mean));
    }
    __syncthreads();

    int curb = t0 >> 8;
    stage(curb);

    ull biasv[8];
#pragma unroll
    for (int j = 0; j < 8; j++) biasv[j] = sbias2[o0 + j];

    int buf = 0;
#pragma unroll 1
    for (int s = t0; s < t1; s++) {
        if (s + 1 < t1) { CP_WAIT1(); } else { CP_WAIT0(); }
        __syncthreads();                    // slot(s) full; slot(s+2) free; sCF2 visible
        const int b = s >> 8;
        if (b != curb) { stage(b); curb = b; __syncthreads(); }
        if (s + 2 < t1) {
            int nb = buf + 2; if (nb >= 3) nb -= 3;
            issue(s + 2, nb);               // overlaps with compute below
        }

        ull acc[8][2][2];
#pragma unroll
        for (int j = 0; j < 8; j++) {
            acc[j][0][0] = biasv[j]; acc[j][0][1] = biasv[j];
            acc[j][1][0] = biasv[j]; acc[j][1][1] = biasv[j];
        }

#pragma unroll
        for (int c = 0; c < C_; c++) {
            const float* smc = sM[buf][c];
            ulonglong2 mq0 = reinterpret_cast<const ulonglong2*>(smc)[lane];
            ulonglong2 mq1 = reinterpret_cast<const ulonglong2*>(smc)[lane + 32];
            const ulonglong2* cfp = reinterpret_cast<const ulonglong2*>(&sCF2[c * O_ + o0]);
            ulonglong2 p0 = cfp[0], p1 = cfp[1], p2 = cfp[2], p3 = cfp[3];
            FFMA2(acc[0][0][0], p0.x, mq0.x); FFMA2(acc[0][0][1], p0.x, mq0.y);
            FFMA2(acc[0][1][0], p0.x, mq1.x); FFMA2(acc[0][1][1], p0.x, mq1.y);
            FFMA2(acc[1][0][0], p0.y, mq0.x); FFMA2(acc[1][0][1], p0.y, mq0.y);
            FFMA2(acc[1][1][0], p0.y, mq1.x); FFMA2(acc[1][1][1], p0.y, mq1.y);
            FFMA2(acc[2][0][0], p1.x, mq0.x); FFMA2(acc[2][0][1], p1.x, mq0.y);
            FFMA2(acc[2][1][0], p1.x, mq1.x); FFMA2(acc[2][1][1], p1.x, mq1.y);
            FFMA2(acc[3][0][0], p1.y, mq0.x); FFMA2(acc[3][0][1], p1.y, mq0.y);
            FFMA2(acc[3][1][0], p1.y, mq1.x); FFMA2(acc[3][1][1], p1.y, mq1.y);
            FFMA2(acc[4][0][0], p2.x, mq0.x); FFMA2(acc[4][0][1], p2.x, mq0.y);
            FFMA2(acc[4][1][0], p2.x, mq1.x); FFMA2(acc[4][1][1], p2.x, mq1.y);
            FFMA2(acc[5][0][0], p2.y, mq0.x); FFMA2(acc[5][0][1], p2.y, mq0.y);
            FFMA2(acc[5][1][0], p2.y, mq1.x); FFMA2(acc[5][1][1], p2.y, mq1.y);
            FFMA2(acc[6][0][0], p3.x, mq0.x); FFMA2(acc[6][0][1], p3.x, mq0.y);
            FFMA2(acc[6][1][0], p3.x, mq1.x); FFMA2(acc[6][1][1], p3.x, mq1.y);
            FFMA2(acc[7][0][0], p3.y, mq0.x); FFMA2(acc[7][0][1], p3.y, mq0.y);
            FFMA2(acc[7][1][0], p3.y, mq1.x); FFMA2(acc[7][1][1], p3.y, mq1.y);
        }

        // epilogue: ReLU + STG.128 (fire-and-forget, overlaps next iteration)
        const int px = (s & 255) * KM_PX;
        float* ob = out + (size_t)b * O_ * HW_ + px;
#pragma unroll
        for (int j = 0; j < 8; j++) {
            float4* orow = reinterpret_cast<float4*>(ob + (size_t)(o0 + j) * HW_);
#pragma unroll
            for (int qd = 0; qd < 2; qd++) {
                ull a0 = acc[j][qd][0], a1 = acc[j][qd][1];
                float4 v = make_float4(
                    fmaxf(__uint_as_float((uint)(a0 & 0xffffffffu)), 0.f),
                    fmaxf(__uint_as_float((uint)(a0 >> 32)),         0.f),
                    fmaxf(__uint_as_float((uint)(a1 & 0xffffffffu)), 0.f),
                    fmaxf(__uint_as_float((uint)(a1 >> 32)),         0.f));
                orow[lane + qd * 32] = v;
            }
        }
        buf = (buf + 1 == 3) ? 0 : buf + 1;
    }
}

// ---------------- launcher ----------------------------------------------------
extern "C" void kernel_launch(void* const* d_in, const int* in_sizes, int n_in,
                              void* d_out, int out_size) {
    const float* feat   = (const float*)d_in[0];
    const float* mask   = (const float*)d_in[1];
    const float* conv_w = (const float*)d_in[2];
    const float* conv_b = (const float*)d_in[3];
    const float* gamma  = (const float*)d_in[4];
    const float* beta   = (const float*)d_in[5];
    float* out = (float*)d_out;

    kstats<<<dim3(KS_CHUNKS, B_), 672>>>(mask);
    kprep_a<<<B_, 256>>>(feat, conv_w);
    kmain<<<KM_NBLK, 512>>>(mask, out, conv_b, gamma, beta);
}

// round 15
// speedup vs baseline: 1.2382x; 1.2382x over previous
#include <cuda_runtime.h>
#include <cstdint>

#define B_  8
#define C_  21
#define D_  64
#define O_  128
#define HW_ 65536
#define N_TOT (B_ * HW_)

typedef unsigned long long ull;
typedef unsigned int uint;

#define FFMA2(acc, a, b) asm("fma.rn.f32x2 %0, %1, %2, %0;" : "+l"(acc) : "l"(a), "l"(b))
#define FADD2(acc, a)    asm("add.rn.f32x2 %0, %0, %1;"     : "+l"(acc) : "l"(a))

// ---------------- device scratch ---------------------------------------------
#define KS_CHUNKS 18                  // 18*8 = 144 blocks = one clean wave
#define NVAL 252                      // 231 triangle + 21 sums
__device__ float g_Gp[KS_CHUNKS * B_ * NVAL];   // per-block stat partials
__device__ float g_W2T[B_ * C_ * O_];           // combined weights [b][c][o]
__device__ float g_partY[B_ * O_];
__device__ float g_partQ[B_ * O_];

// ---------------- helpers ------------------------------------------------------
__device__ __forceinline__ void cp16(void* dst, const void* src) {
    uint s = (uint)__cvta_generic_to_shared(dst);
    asm volatile("cp.async.cg.shared.global [%0], [%1], 16;" :: "r"(s), "l"(src));
}
#define CP_COMMIT() asm volatile("cp.async.commit_group;" ::: "memory")
#define CP_WAIT1()  asm volatile("cp.async.wait_group 1;" ::: "memory")
#define CP_WAIT0()  asm volatile("cp.async.wait_group 0;" ::: "memory")

__device__ __forceinline__ float pairsum(ull a) {
    return __uint_as_float((uint)(a & 0xffffffffu)) + __uint_as_float((uint)(a >> 32));
}
__device__ __forceinline__ ull lo64(float4 v) {
    return ((ull)__float_as_uint(v.y) << 32) | __float_as_uint(v.x);
}
__device__ __forceinline__ ull hi64(float4 v) {
    return ((ull)__float_as_uint(v.w) << 32) | __float_as_uint(v.z);
}
__device__ __forceinline__ ull dup2(float x) {
    ull r;
    asm("mov.b64 %0, {%1, %1};" : "=l"(r) : "f"(x));
    return r;
}
__device__ __forceinline__ float wredsum(float v) {
#pragma unroll
    for (int off = 16; off; off >>= 1) v += __shfl_xor_sync(0xffffffffu, v, off);
    return v;
}

// ---------------- kstats: G6 triangular Gram, LDG streaming + row prefetch ----
// grid (18, 8), 672 threads = 21 warps, 144 blocks = ONE wave.
// Rows in 6 groups {0-3,4-7,8-11,12-14,15-17,18-20}; each warp owns one
// (group x group) block of the lower triangle. Row loads for u+1 are
// prefetched (MLP x2) ONLY on tasks where registers stay well under the
// 96-reg cap (NR+NC<=7 or DIAG) -- the 4x4 off-diag tasks keep R13 form.
template <int R0, int NR, int C0, int NC, bool DIAG>
__device__ __forceinline__ void gram_task(const float* __restrict__ mb,
                                          int u0, int u1, int lane,
                                          float* __restrict__ gp) {
    constexpr bool PREF = DIAG || (NR + NC <= 7);

    ull acc[NR][NC];
    ull ss[NR];
#pragma unroll
    for (int i = 0; i < NR; i++) {
        ss[i] = 0ull;
#pragma unroll
        for (int j = 0; j < NC; j++) acc[i][j] = 0ull;
    }

    ull ra[NR], rb[NR];
    if (PREF) {
        const int q = u0 * 32 + lane;
#pragma unroll
        for (int i = 0; i < NR; i++) {
            float4 v = reinterpret_cast<const float4*>(mb + (size_t)(R0 + i) * HW_)[q];
            ra[i] = lo64(v); rb[i] = hi64(v);
        }
    }

#pragma unroll 1
    for (int u = u0; u < u1; u++) {
        const int q = u * 32 + lane;

        if (!PREF) {
            // R13 form: load rows in-loop
#pragma unroll
            for (int i = 0; i < NR; i++) {
                float4 v = reinterpret_cast<const float4*>(mb + (size_t)(R0 + i) * HW_)[q];
                ra[i] = lo64(v); rb[i] = hi64(v);
            }
        }

        // prefetch next iteration's rows (PREF tasks only)
        ull nra[PREF ? NR : 1], nrb[PREF ? NR : 1];
        if (PREF && u + 1 < u1) {
            const int qn = (u + 1) * 32 + lane;
#pragma unroll
            for (int i = 0; i < NR; i++) {
                float4 v = reinterpret_cast<const float4*>(mb + (size_t)(R0 + i) * HW_)[qn];
                nra[i] = lo64(v); nrb[i] = hi64(v);
            }
        }

        if (DIAG) {
#pragma unroll
            for (int i = 0; i < NR; i++) { FADD2(ss[i], ra[i]); FADD2(ss[i], rb[i]); }
        }

        ull ca[NC], cb[NC];
#pragma unroll
        for (int j = 0; j < NC; j++) {
            if (DIAG) { ca[j] = ra[j]; cb[j] = rb[j]; }
            else {
                float4 v = reinterpret_cast<const float4*>(mb + (size_t)(C0 + j) * HW_)[q];
                ca[j] = lo64(v); cb[j] = hi64(v);
            }
        }
#pragma unroll
        for (int i = 0; i < NR; i++)
#pragma unroll
            for (int j = 0; j < NC; j++) {
                if (DIAG && j > i) continue;     // lower triangle only
                FFMA2(acc[i][j], ra[i], ca[j]);
                FFMA2(acc[i][j], rb[i], cb[j]);
            }

        if (PREF && u + 1 < u1) {
#pragma unroll
            for (int i = 0; i < NR; i++) { ra[i] = nra[i]; rb[i] = nrb[i]; }
        }
    }

#pragma unroll
    for (int i = 0; i < NR; i++) {
#pragma unroll
        for (int j = 0; j < NC; j++) {
            if (DIAG && j > i) continue;
            float v = wredsum(pairsum(acc[i][j]));
            const int r = R0 + i, c = C0 + j;
            if (lane == 0) gp[r * (r + 1) / 2 + c] = v;
        }
        if (DIAG) {
            float v = wredsum(pairsum(ss[i]));
            if (lane == 0) gp[231 + R0 + i] = v;
        }
    }
}

__global__ __launch_bounds__(672) void kstats(const float* __restrict__ mask) {
    const int b = blockIdx.y;
    const int bidx = blockIdx.x;
    const int wid = threadIdx.x >> 5;
    const int lane = threadIdx.x & 31;

    const int u0 = (bidx * 512) / KS_CHUNKS;
    const int u1 = ((bidx + 1) * 512) / KS_CHUNKS;

    const float* mb = mask + (size_t)b * C_ * HW_;
    float* gp = g_Gp + (bidx * B_ + b) * NVAL;

    switch (wid) {
        case 0:  gram_task< 0, 4,  0, 4, true >(mb, u0, u1, lane, gp); break;
        case 1:  gram_task< 4, 4,  4, 4, true >(mb, u0, u1, lane, gp); break;
        case 2:  gram_task< 8, 4,  8, 4, true >(mb, u0, u1, lane, gp); break;
        case 3:  gram_task<12, 3, 12, 3, true >(mb, u0, u1, lane, gp); break;
        case 4:  gram_task<15, 3, 15, 3, true >(mb, u0, u1, lane, gp); break;
        case 5:  gram_task<18, 3, 18, 3, true >(mb, u0, u1, lane, gp); break;
        case 6:  gram_task< 4, 4,  0, 4, false>(mb, u0, u1, lane, gp); break;
        case 7:  gram_task< 8, 4,  0, 4, false>(mb, u0, u1, lane, gp); break;
        case 8:  gram_task< 8, 4,  4, 4, false>(mb, u0, u1, lane, gp); break;
        case 9:  gram_task<12, 3,  0, 4, false>(mb, u0, u1, lane, gp); break;
        case 10: gram_task<12, 3,  4, 4, false>(mb, u0, u1, lane, gp); break;
        case 11: gram_task<12, 3,  8, 4, false>(mb, u0, u1, lane, gp); break;
        case 12: gram_task<15, 3,  0, 4, false>(mb, u0, u1, lane, gp); break;
        case 13: gram_task<15, 3,  4, 4, false>(mb, u0, u1, lane, gp); break;
        case 14: gram_task<15, 3,  8, 4, false>(mb, u0, u1, lane, gp); break;
        case 15: gram_task<15, 3, 12, 3, false>(mb, u0, u1, lane, gp); break;
        case 16: gram_task<18, 3,  0, 4, false>(mb, u0, u1, lane, gp); break;
        case 17: gram_task<18, 3,  4, 4, false>(mb, u0, u1, lane, gp); break;
        case 18: gram_task<18, 3,  8, 4, false>(mb, u0, u1, lane, gp); break;
        case 19: gram_task<18, 3, 12, 3, false>(mb, u0, u1, lane, gp); break;
        default: gram_task<18, 3, 15, 3, false>(mb, u0, u1, lane, gp); break;
    }
}

// ---------------- kprep_a: W2T + partial reduce + quadratic forms -------------
__global__ __launch_bounds__(256) void kprep_a(const float* __restrict__ feat,
                                               const float* __restrict__ conv_w) {
    __shared__ float sWT[D_ * 129 + 32];
    __shared__ float sF[C_ * D_];
    __shared__ float sG[231];
    __shared__ float sS[C_];
    const int b = blockIdx.x;
    const int tid = threadIdx.x;

    for (int i = tid; i < O_ * D_; i += 256) {
        int o = i >> 6, d = i & 63;
        sWT[d * 129 + o] = conv_w[i];
    }
    for (int i = tid; i < C_ * D_; i += 256) sF[i] = feat[b * C_ * D_ + i];
    for (int v = tid; v < NVAL; v += 256) {
        float s = 0.f;
#pragma unroll
        for (int ch = 0; ch < KS_CHUNKS; ch++) s += g_Gp[(ch * B_ + b) * NVAL + v];
        if (v < 231) sG[v] = s;
        else         sS[v - 231] = s;
    }
    __syncthreads();

    for (int idx = tid; idx < C_ * O_; idx += 256) {
        int c = idx >> 7, o = idx & 127;
        float s = 0.f;
#pragma unroll
        for (int d = 0; d < D_; d++)
            s = fmaf(sWT[d * 129 + o], sF[c * D_ + d], s);
        g_W2T[b * C_ * O_ + idx] = s;
    }
    __syncthreads();

    if (tid < O_) {
        const int o = tid;
        float w[C_];
#pragma unroll
        for (int c = 0; c < C_; c++) w[c] = g_W2T[(b * C_ + c) * O_ + o];
        float sumY = 0.f;
#pragma unroll
        for (int c = 0; c < C_; c++) sumY = fmaf(w[c], sS[c], sumY);
        float sumQ = 0.f;
#pragma unroll
        for (int r = 0; r < C_; r++) {
            const int tr = r * (r + 1) / 2;
            float t = sG[tr + r] * w[r];
#pragma unroll
            for (int c = 0; c < r; c++) t = fmaf(2.f * sG[tr + c], w[c], t);
            sumQ = fmaf(w[r], t, sumQ);
        }
        g_partY[b * O_ + o] = sumY;
        g_partQ[b * O_ + o] = sumQ;
    }
}

// ---------------- kmain: R13-proven core (BN prologue, 3-slot ring) -----------
// 148 blocks x 512 threads (16 warps/SM). Subtile = 256 px x 128 ch.
// Warp = 8 channels; thread = 2 quads (8 px) x 8 ch. Mask: 3-deep cp.async
// ring, ONE barrier per subtile. Coefs: scalar smem + ALU dup (mov.b64).
#define KM_NBLK 148
#define KM_NT   2048
#define KM_PX   256

__global__ __launch_bounds__(512) void kmain(const float* __restrict__ mask,
                                             float* __restrict__ out,
                                             const float* __restrict__ conv_b,
                                             const float* __restrict__ gamma,
                                             const float* __restrict__ beta) {
    __shared__ __align__(16) float sM[3][C_][KM_PX];   // 64512 B
    __shared__ __align__(16) float sCF[C_ * O_];       // 10752 B
    __shared__ __align__(16) float salpha[O_];
    __shared__ float sbias[O_];

    const int tid = threadIdx.x;
    const int wid = tid >> 5;
    const int lane = tid & 31;
    const int o0 = wid * 8;

    const int bid = blockIdx.x;
    const int t0 = (bid * KM_NT) / KM_NBLK;
    const int t1 = ((bid + 1) * KM_NT) / KM_NBLK;

    auto issue = [&](int s, int slot) {
        const int b = s >> 8;
        const int px = (s & 255) * KM_PX;
        const float* mb = mask + (size_t)b * C_ * HW_ + px;
        for (int u = tid; u < C_ * (KM_PX / 4); u += 512) {
            int c = u >> 6, q = u & 63;
            cp16(&sM[slot][c][q * 4], mb + (size_t)c * HW_ + q * 4);
        }
        CP_COMMIT();
    };
    auto stage = [&](int b) {
        const float4* src = reinterpret_cast<const float4*>(g_W2T + (size_t)b * C_ * O_);
        float4* dst = reinterpret_cast<float4*>(sCF);
        for (int i = tid; i < C_ * O_ / 4; i += 512) {
            float4 w = src[i];
            const float4 a = *reinterpret_cast<const float4*>(&salpha[(i & 31) << 2]);
            dst[i] = make_float4(w.x * a.x, w.y * a.y, w.z * a.z, w.w * a.w);
        }
    };

    // prologue: start the cp.async pipeline, then compute alpha/bias
    issue(t0, 0);
    if (t0 + 1 < t1) issue(t0 + 1, 1);

    if (tid < O_) {
        const int o = tid;
        float sumY = 0.f, sumQ = 0.f;
#pragma unroll
        for (int bb = 0; bb < B_; bb++) {
            sumY += g_partY[bb * O_ + o];
            sumQ += g_partQ[bb * O_ + o];
        }
        const float invN = 1.f / (float)N_TOT;
        const float b0 = conv_b[o];
        const float es = sumY * invN;
        const float mean = b0 + es;
        const float ey2 = sumQ * invN + 2.f * b0 * es + b0 * b0;
        const float var = ey2 - mean * mean;
        const float alpha = gamma[o] * rsqrtf(var + 1e-5f);
        salpha[o] = alpha;
        sbias[o] = beta[o] + alpha * (b0 - mean);
    }
    __syncthreads();

    int curb = t0 >> 8;
    stage(curb);

    float biasv[8];
#pragma unroll
    for (int j = 0; j < 8; j++) biasv[j] = sbias[o0 + j];

    int buf = 0;
#pragma unroll 1
    for (int s = t0; s < t1; s++) {
        if (s + 1 < t1) { CP_WAIT1(); } else { CP_WAIT0(); }
        __syncthreads();                    // slot(s) full; slot(s+2) free; sCF visible
        const int b = s >> 8;
        if (b != curb) { stage(b); curb = b; __syncthreads(); }
        if (s + 2 < t1) {
            int nb = buf + 2; if (nb >= 3) nb -= 3;
            issue(s + 2, nb);               // overlaps with compute below
        }

        ull acc[8][2][2];
#pragma unroll
        for (int j = 0; j < 8; j++) {
            ull d = dup2(biasv[j]);
            acc[j][0][0] = d; acc[j][0][1] = d;
            acc[j][1][0] = d; acc[j][1][1] = d;
        }

#pragma unroll
        for (int c = 0; c < C_; c++) {
            const float* smc = sM[buf][c];
            ulonglong2 mq0 = reinterpret_cast<const ulonglong2*>(smc)[lane];
            ulonglong2 mq1 = reinterpret_cast<const ulonglong2*>(smc)[lane + 32];
            float4 w0 = *reinterpret_cast<const float4*>(&sCF[c * O_ + o0]);
            float4 w1 = *reinterpret_cast<const float4*>(&sCF[c * O_ + o0 + 4]);
            ull c0 = dup2(w0.x), c1 = dup2(w0.y), c2 = dup2(w0.z), c3 = dup2(w0.w);
            ull c4 = dup2(w1.x), c5 = dup2(w1.y), c6 = dup2(w1.z), c7 = dup2(w1.w);
            FFMA2(acc[0][0][0], c0, mq0.x); FFMA2(acc[0][0][1], c0, mq0.y);
            FFMA2(acc[0][1][0], c0, mq1.x); FFMA2(acc[0][1][1], c0, mq1.y);
            FFMA2(acc[1][0][0], c1, mq0.x); FFMA2(acc[1][0][1], c1, mq0.y);
            FFMA2(acc[1][1][0], c1, mq1.x); FFMA2(acc[1][1][1], c1, mq1.y);
            FFMA2(acc[2][0][0], c2, mq0.x); FFMA2(acc[2][0][1], c2, mq0.y);
            FFMA2(acc[2][1][0], c2, mq1.x); FFMA2(acc[2][1][1], c2, mq1.y);
            FFMA2(acc[3][0][0], c3, mq0.x); FFMA2(acc[3][0][1], c3, mq0.y);
            FFMA2(acc[3][1][0], c3, mq1.x); FFMA2(acc[3][1][1], c3, mq1.y);
            FFMA2(acc[4][0][0], c4, mq0.x); FFMA2(acc[4][0][1], c4, mq0.y);
            FFMA2(acc[4][1][0], c4, mq1.x); FFMA2(acc[4][1][1], c4, mq1.y);
            FFMA2(acc[5][0][0], c5, mq0.x); FFMA2(acc[5][0][1], c5, mq0.y);
            FFMA2(acc[5][1][0], c5, mq1.x); FFMA2(acc[5][1][1], c5, mq1.y);
            FFMA2(acc[6][0][0], c6, mq0.x); FFMA2(acc[6][0][1], c6, mq0.y);
            FFMA2(acc[6][1][0], c6, mq1.x); FFMA2(acc[6][1][1], c6, mq1.y);
            FFMA2(acc[7][0][0], c7, mq0.x); FFMA2(acc[7][0][1], c7, mq0.y);
            FFMA2(acc[7][1][0], c7, mq1.x); FFMA2(acc[7][1][1], c7, mq1.y);
        }

        // epilogue: ReLU + STG.128 (fire-and-forget, overlaps next iteration)
        const int px = (s & 255) * KM_PX;
        float* ob = out + (size_t)b * O_ * HW_ + px;
#pragma unroll
        for (int j = 0; j < 8; j++) {
            float4* orow = reinterpret_cast<float4*>(ob + (size_t)(o0 + j) * HW_);
#pragma unroll
            for (int qd = 0; qd < 2; qd++) {
                ull a0 = acc[j][qd][0], a1 = acc[j][qd][1];
                float4 v = make_float4(
                    fmaxf(__uint_as_float((uint)(a0 & 0xffffffffu)), 0.f),
                    fmaxf(__uint_as_float((uint)(a0 >> 32)),         0.f),
                    fmaxf(__uint_as_float((uint)(a1 & 0xffffffffu)), 0.f),
                    fmaxf(__uint_as_float((uint)(a1 >> 32)),         0.f));
                orow[lane + qd * 32] = v;
            }
        }
        buf = (buf + 1 == 3) ? 0 : buf + 1;
    }
}

// ---------------- launcher ----------------------------------------------------
extern "C" void kernel_launch(void* const* d_in, const int* in_sizes, int n_in,
                              void* d_out, int out_size) {
    const float* feat   = (const float*)d_in[0];
    const float* mask   = (const float*)d_in[1];
    const float* conv_w = (const float*)d_in[2];
    const float* conv_b = (const float*)d_in[3];
    const float* gamma  = (const float*)d_in[4];
    const float* beta   = (const float*)d_in[5];
    float* out = (float*)d_out;

    kstats<<<dim3(KS_CHUNKS, B_), 672>>>(mask);
    kprep_a<<<B_, 256>>>(feat, conv_w);
    kmain<<<KM_NBLK, 512>>>(mask, out, conv_b, gamma, beta);
}